// round 9
// baseline (speedup 1.0000x reference)
#include <cuda_runtime.h>

// ContourChamferLoss on GB300 (sm_103a) — round 9
// Exact NN via 32x32 spatial grid; WARP-PER-QUERY search (576K threads)
// to bury gather latency. Deterministic ticketed reduction.

#define NP_TOT 64000
#define NR_TOT 80000
#define NP     8000
#define NR     10000
#define NTOT   (NP + NR)

// exact f32 replication of jnp.linspace(0, n-1, n//8) index math
#define DELTA_P ((float)(NP_TOT - 1) / (float)(NP - 1))
#define DELTA_R ((float)(NR_TOT - 1) / (float)(NR - 1))

#define GK    32                 // grid cells per dimension
#define NCELL (GK * GK)          // 1024
#define CS    (1.0f / (float)GK) // cell size
#define CAP   128                // slots per cell (mean ~10)

#define STPB     256
#define S_BLOCKS ((NTOT + STPB - 1) / STPB)      // 71

#define TPB      256
#define WPB      (TPB / 32)                      // 8 queries per block
#define NBLK     ((NTOT + WPB - 1) / WPB)        // 2250

#define FULLM 0xFFFFFFFFu

// ---- device scratch (static zero-init; no allocation allowed) ----
// Counters start zero (static init) and are re-zeroed by the last search block
// each run -> graph replays see zeroed counters. Slot order within a cell may
// vary, but min over a set is order-independent -> deterministic output.
__device__ int    g_cntP[NCELL];
__device__ int    g_cntR[NCELL];
__device__ float2 g_ptsP[NCELL * CAP];
__device__ float2 g_ptsR[NCELL * CAP];
__device__ float  g_part[NBLK];
__device__ unsigned int g_ctr;

__device__ __forceinline__ int clamp_cell(int c) {
    return c < 0 ? 0 : (c > GK - 1 ? GK - 1 : c);
}

// ---------------- scatter: subsample gather + bucket append ----------------
__global__ __launch_bounds__(STPB) void scatter_kernel(const float* __restrict__ pc,
                                                       const float* __restrict__ ref) {
    int k = blockIdx.x * STPB + threadIdx.x;
    if (k < NP) {
        int i = (int)((float)k * DELTA_P);
        float2 p = *reinterpret_cast<const float2*>(pc + 2 * i);
        int cx = clamp_cell((int)(p.x * (float)GK));
        int cy = clamp_cell((int)(p.y * (float)GK));
        int c = cy * GK + cx;
        int s = atomicAdd(&g_cntP[c], 1);
        if (s < CAP) g_ptsP[c * CAP + s] = p;
    } else if (k < NTOT) {
        int j = k - NP;
        int i = (int)((float)j * DELTA_R);
        float2 p = *reinterpret_cast<const float2*>(ref + 2 * i);
        int cx = clamp_cell((int)(p.x * (float)GK));
        int cy = clamp_cell((int)(p.y * (float)GK));
        int c = cy * GK + cx;
        int s = atomicAdd(&g_cntR[c], 1);
        if (s < CAP) g_ptsR[c * CAP + s] = p;
    }
}

// ---------------- warp-per-query search + fused deterministic reduction -----
__global__ __launch_bounds__(TPB) void search_kernel(const float* __restrict__ pc,
                                                     const float* __restrict__ ref,
                                                     float* __restrict__ out) {
    int lane  = threadIdx.x & 31;
    int wslot = threadIdx.x >> 5;
    int q = blockIdx.x * WPB + wslot;

    float v = 0.f;   // lane-0 contribution of this warp

    if (q < NTOT) {
        const float2* pts;
        const int* cnt;
        const float* own;
        float delta, scale;
        int k;
        if (q < NP) {
            pts = g_ptsR; cnt = g_cntR; own = pc;
            delta = DELTA_P; scale = 0.5f / (float)NP; k = q;
        } else {
            pts = g_ptsP; cnt = g_cntP; own = ref;
            delta = DELTA_R; scale = 0.5f / (float)NR; k = q - NP;
        }

        int i = (int)((float)k * delta);
        float2 p = *reinterpret_cast<const float2*>(own + 2 * i);  // uniform: 1 req/warp
        float px = p.x, py = p.y;
        int cx = clamp_cell((int)(px * (float)GK));
        int cy = clamp_cell((int)(py * (float)GK));

        // lanes 0..8 fetch the 3x3 cell counts in parallel
        int myCell = 0, myM = 0;
        if (lane < 9) {
            int yy = cy + lane / 3 - 1;
            int xx = cx + lane % 3 - 1;
            if (yy >= 0 && yy < GK && xx >= 0 && xx < GK) {
                myCell = yy * GK + xx;
                int m = cnt[myCell];
                myM = m < CAP ? m : CAP;
            }
        }

        float dmin = 1e30f;

        // 9 independent candidate batches; lanes stride slots (MLP ~9)
        #pragma unroll
        for (int c = 0; c < 9; c++) {
            int cell = __shfl_sync(FULLM, myCell, c);
            int m    = __shfl_sync(FULLM, myM, c);
            for (int s = lane; s < m; s += 32) {
                float2 pp = pts[cell * CAP + s];
                float ddx = px - pp.x;
                float ddy = py - pp.y;
                dmin = fminf(dmin, fmaf(ddx, ddx, ddy * ddy));
            }
        }

        // warp min-reduce (result uniform across lanes)
        #pragma unroll
        for (int o = 16; o > 0; o >>= 1)
            dmin = fminf(dmin, __shfl_xor_sync(FULLM, dmin, o));

        // expanding rings (rare): after radius-r square, coverage radius r*CS
        int r = 1;
        float cov = CS;
        while (dmin > cov * cov && r < GK - 1) {
            r++;
            cov = (float)r * CS;
            for (int dy = -r; dy <= r; dy++) {
                int yy = cy + dy;
                if (yy < 0 || yy >= GK) continue;
                int xlo, xhi, xstep;
                if (dy == -r || dy == r) { xlo = cx - r; xhi = cx + r; xstep = 1; }
                else                     { xlo = cx - r; xhi = cx + r; xstep = 2 * r; }
                for (int xx = xlo; xx <= xhi; xx += xstep) {
                    if (xx < 0 || xx >= GK) continue;
                    int cell = yy * GK + xx;
                    int m = cnt[cell];           // uniform load
                    m = m < CAP ? m : CAP;
                    for (int s = lane; s < m; s += 32) {
                        float2 pp = pts[cell * CAP + s];
                        float ddx = px - pp.x;
                        float ddy = py - pp.y;
                        dmin = fminf(dmin, fmaf(ddx, ddx, ddy * ddy));
                    }
                }
            }
            #pragma unroll
            for (int o = 16; o > 0; o >>= 1)
                dmin = fminf(dmin, __shfl_xor_sync(FULLM, dmin, o));
        }

        if (lane == 0) v = sqrtf(dmin) * scale;
    }

    // ---- block partial (fixed slots, fixed order -> deterministic) ----
    __shared__ float sw[WPB];
    if (lane == 0) sw[wslot] = v;
    __syncthreads();

    __shared__ int lastf;
    if (threadIdx.x == 0) {
        float s = 0.f;
        #pragma unroll
        for (int w = 0; w < WPB; w++) s += sw[w];
        g_part[blockIdx.x] = s;
        __threadfence();
        unsigned int done = atomicAdd(&g_ctr, 1u);
        lastf = (done == NBLK - 1) ? 1 : 0;
    }
    __syncthreads();

    // ---- last-arriving block: deterministic final combine + state reset ----
    if (lastf) {
        if (threadIdx.x == 0) __threadfence();
        __syncthreads();

        int tid = threadIdx.x;
        float acc = 0.f;
        for (int b = tid; b < NBLK; b += TPB)   // fixed per-thread order
            acc += g_part[b];

        #pragma unroll
        for (int o = 16; o > 0; o >>= 1)
            acc += __shfl_xor_sync(FULLM, acc, o);

        __shared__ float sw2[TPB / 32];
        if ((tid & 31) == 0) sw2[tid >> 5] = acc;
        __syncthreads();

        if (tid == 0) {
            float t = 0.f;
            #pragma unroll
            for (int w = 0; w < TPB / 32; w++) t += sw2[w];
            out[0] = t;
            g_ctr = 0;
        }

        // zero bucket counters for next graph replay (all readers done)
        for (int c = tid; c < NCELL; c += TPB) {
            g_cntP[c] = 0;
            g_cntR[c] = 0;
        }
    }
}

extern "C" void kernel_launch(void* const* d_in, const int* in_sizes, int n_in,
                              void* d_out, int out_size) {
    const float* pc  = (const float*)d_in[0];   // img_render_points (64000 x 2)
    const float* ref = (const float*)d_in[1];   // ref point cloud   (80000 x 2)

    scatter_kernel<<<S_BLOCKS, STPB>>>(pc, ref);
    search_kernel<<<NBLK, TPB>>>(pc, ref, (float*)d_out);
}